// round 7
// baseline (speedup 1.0000x reference)
#include <cuda_runtime.h>
#include <cuda_bf16.h>
#include <math_constants.h>
#include <cstdint>
#include <cstddef>

// Problem constants
#define BATCH   8
#define SEQ     1024
#define DIM     512
#define HEADS   8
#define DHEAD   64
#define MROWS   (BATCH * SEQ)        // 8192
#define LOCALB  16

// Scratch (device globals; allocation is forbidden)
__device__ float g_q[MROWS * DIM];    // head-split [b][h][s][d]
__device__ float g_k[MROWS * DIM];
__device__ float g_v[MROWS * DIM];
__device__ float g_att[MROWS * DIM];  // merged-head [b][s][h*64+d]

// ---------------------------------------------------------------------------
// tf32 tensor-core GEMM (exact R5 proven version):
// 128x128 block tile, BK=16, double-buffered smem + register prefetch.
// 8 warps, each 64x32 (4x4 tiles of m16n8k8 tf32 mma).
// ---------------------------------------------------------------------------
#define BK 16
#define APITCH 20
#define BPITCH 136

__device__ __forceinline__ uint32_t f2tf32(float f) {
    uint32_t r;
    asm("cvt.rna.tf32.f32 %0, %1;" : "=r"(r) : "f"(f));
    return r;
}

__device__ __forceinline__ void mma_tf32(
    float& c0, float& c1, float& c2, float& c3,
    uint32_t a0, uint32_t a1, uint32_t a2, uint32_t a3,
    uint32_t b0, uint32_t b1)
{
    asm volatile(
        "mma.sync.aligned.m16n8k8.row.col.f32.tf32.tf32.f32 "
        "{%0,%1,%2,%3}, {%4,%5,%6,%7}, {%8,%9}, {%0,%1,%2,%3};"
        : "+f"(c0), "+f"(c1), "+f"(c2), "+f"(c3)
        : "r"(a0), "r"(a1), "r"(a2), "r"(a3), "r"(b0), "r"(b1));
}

__device__ __forceinline__ void gemm_tf32_body(
    const float* __restrict__ A, const float* __restrict__ W,
    const float* __restrict__ bias, float* __restrict__ C,
    int headsplit, int bx, int by)
{
    __shared__ float As[2][128][APITCH];
    __shared__ float Bs[2][BK][BPITCH];

    const int tid  = threadIdx.x;
    const int warp = tid >> 5;
    const int lane = tid & 31;
    const int g    = lane >> 2;
    const int tig  = lane & 3;

    const int warp_m = warp >> 2;
    const int warp_n = warp & 3;

    const float* Aptr = A + (size_t)(by * 128) * DIM;
    const float* Wptr = W + bx * 128;

    const int arow = tid >> 2;
    const int ac4  = (tid & 3) * 4;
    const int brow = tid >> 5;
    const int bc4  = (tid & 31) * 4;

    float c[4][4][4];
#pragma unroll
    for (int i = 0; i < 4; i++)
#pragma unroll
        for (int j = 0; j < 4; j++)
#pragma unroll
            for (int r = 0; r < 4; r++) c[i][j][r] = 0.f;

    float4 ra0, ra1, rb0, rb1;

    auto loadG = [&](int k0) {
        ra0 = *(const float4*)(Aptr + (size_t)arow * DIM + k0 + ac4);
        ra1 = *(const float4*)(Aptr + (size_t)(arow + 64) * DIM + k0 + ac4);
        rb0 = *(const float4*)(Wptr + (size_t)(k0 + brow) * DIM + bc4);
        rb1 = *(const float4*)(Wptr + (size_t)(k0 + brow + 8) * DIM + bc4);
    };
    auto storeS = [&](int buf) {
        float4 t;
        t.x = __uint_as_float(f2tf32(ra0.x)); t.y = __uint_as_float(f2tf32(ra0.y));
        t.z = __uint_as_float(f2tf32(ra0.z)); t.w = __uint_as_float(f2tf32(ra0.w));
        *(float4*)&As[buf][arow][ac4] = t;
        t.x = __uint_as_float(f2tf32(ra1.x)); t.y = __uint_as_float(f2tf32(ra1.y));
        t.z = __uint_as_float(f2tf32(ra1.z)); t.w = __uint_as_float(f2tf32(ra1.w));
        *(float4*)&As[buf][arow + 64][ac4] = t;
        t.x = __uint_as_float(f2tf32(rb0.x)); t.y = __uint_as_float(f2tf32(rb0.y));
        t.z = __uint_as_float(f2tf32(rb0.z)); t.w = __uint_as_float(f2tf32(rb0.w));
        *(float4*)&Bs[buf][brow][bc4] = t;
        t.x = __uint_as_float(f2tf32(rb1.x)); t.y = __uint_as_float(f2tf32(rb1.y));
        t.z = __uint_as_float(f2tf32(rb1.z)); t.w = __uint_as_float(f2tf32(rb1.w));
        *(float4*)&Bs[buf][brow + 8][bc4] = t;
    };

    loadG(0);
    storeS(0);
    __syncthreads();

    const int NIT = DIM / BK;   // 32
    for (int it = 0; it < NIT; ++it) {
        const int buf = it & 1;
        if (it + 1 < NIT) loadG((it + 1) * BK);

#pragma unroll
        for (int kk = 0; kk < 2; ++kk) {
            const int kb = kk * 8;
            uint32_t af[4][4];
#pragma unroll
            for (int mi = 0; mi < 4; mi++) {
                const int rb = warp_m * 64 + mi * 16;
                af[mi][0] = __float_as_uint(As[buf][rb + g][kb + tig]);
                af[mi][1] = __float_as_uint(As[buf][rb + g + 8][kb + tig]);
                af[mi][2] = __float_as_uint(As[buf][rb + g][kb + tig + 4]);
                af[mi][3] = __float_as_uint(As[buf][rb + g + 8][kb + tig + 4]);
            }
            uint32_t bf[4][2];
#pragma unroll
            for (int nj = 0; nj < 4; nj++) {
                const int cb = warp_n * 32 + nj * 8;
                bf[nj][0] = __float_as_uint(Bs[buf][kb + tig][cb + g]);
                bf[nj][1] = __float_as_uint(Bs[buf][kb + tig + 4][cb + g]);
            }
#pragma unroll
            for (int mi = 0; mi < 4; mi++)
#pragma unroll
                for (int nj = 0; nj < 4; nj++)
                    mma_tf32(c[mi][nj][0], c[mi][nj][1], c[mi][nj][2], c[mi][nj][3],
                             af[mi][0], af[mi][1], af[mi][2], af[mi][3],
                             bf[nj][0], bf[nj][1]);
        }

        if (it + 1 < NIT) storeS((it + 1) & 1);
        __syncthreads();
    }

#pragma unroll
    for (int mi = 0; mi < 4; mi++) {
#pragma unroll
        for (int nj = 0; nj < 4; nj++) {
            const int cb = bx * 128 + warp_n * 32 + nj * 8 + tig * 2;
#pragma unroll
            for (int half = 0; half < 2; half++) {
                const int row = by * 128 + warp_m * 64 + mi * 16 + g + half * 8;
                float v0 = c[mi][nj][half * 2 + 0] + bias[cb];
                float v1 = c[mi][nj][half * 2 + 1] + bias[cb + 1];
                if (headsplit) {
                    int b = row >> 10, s = row & 1023;
                    int h = cb >> 6,  d = cb & 63;
                    size_t o = ((size_t)((b * HEADS + h) * SEQ + s) << 6) + d;
                    C[o]     = v0;
                    C[o + 1] = v1;
                } else {
                    C[(size_t)row * DIM + cb]     = v0;
                    C[(size_t)row * DIM + cb + 1] = v1;
                }
            }
        }
    }
}

__global__ __launch_bounds__(256, 2) void proj_qkv_kernel(
    const float* __restrict__ q,  const float* __restrict__ k,  const float* __restrict__ v,
    const float* __restrict__ Wq, const float* __restrict__ Wk, const float* __restrict__ Wv,
    const float* __restrict__ bq, const float* __restrict__ bk, const float* __restrict__ bv)
{
    const float* A; const float* W; const float* bias; float* C;
    if (blockIdx.z == 0)      { A = q; W = Wq; bias = bq; C = g_q; }
    else if (blockIdx.z == 1) { A = k; W = Wk; bias = bk; C = g_k; }
    else                      { A = v; W = Wv; bias = bv; C = g_v; }
    gemm_tf32_body(A, W, bias, C, 1, blockIdx.x, blockIdx.y);
}

__global__ __launch_bounds__(256, 2) void out_proj_kernel(
    const float* __restrict__ Wo, const float* __restrict__ bo, float* __restrict__ out)
{
    gemm_tf32_body(g_att, Wo, bo, out, 0, blockIdx.x, blockIdx.y);
}

// ---------------------------------------------------------------------------
// Sparse attention, warp-PAIR per query:
// 1024 threads = 32 warps = 16 queries x 2 parity warps.
// Warp (qi, p) processes neighbors n ≡ p (mod 2): half the serial chain.
// Partial softmaxes merged via smem (max-rescale), partial V sums combined.
// ---------------------------------------------------------------------------
#define FULLMASK 0xffffffffu
#define AQ 16                         // queries per block
#define BANDROWS (AQ + LOCALB)        // 32

__global__ __launch_bounds__(1024) void sparse_attn_kernel()
{
    __shared__ float  Kb[BANDROWS][DHEAD];
    __shared__ float  Vb[BANDROWS][DHEAD];
    __shared__ float2 MS[AQ][2];            // per (query, parity): {max, sum}
    __shared__ float  AccS[AQ][2][DHEAD];   // partial V-accumulations

    const int warp   = threadIdx.x >> 5;    // 0..31
    const int lane   = threadIdx.x & 31;
    const int qi     = warp >> 1;           // 0..15 query offset
    const int parity = warp & 1;
    const int s0     = (blockIdx.x & (SEQ / AQ - 1)) * AQ;
    const int bh     = blockIdx.x / (SEQ / AQ);
    const int base   = s0 - LOCALB;

    const float* Kp = g_k + (size_t)bh * SEQ * DHEAD;
    const float* Vp = g_v + (size_t)bh * SEQ * DHEAD;

    // stage band rows [s0-16, s0+15]: 32 rows x 16 f4 x {K,V} = 1024 tasks
    {
        int task  = threadIdx.x;
        int which = task >= BANDROWS * 16;
        int tt    = which ? task - BANDROWS * 16 : task;
        int row   = tt >> 4;
        int c4    = (tt & 15) * 4;
        int j     = base + row;
        if (j >= 0) {
            const float* src = (which ? Vp : Kp) + ((size_t)j << 6) + c4;
            float4 val = *(const float4*)src;
            float* dst = which ? &Vb[row][c4] : &Kb[row][c4];
            *(float4*)dst = val;
        }
        // second half of tasks (threads cover 2048 tasks? no: 1024 threads,
        // 1024 tasks -> exactly covered above for K; V handled by which bit)
    }
    // NOTE: 32*16*2 = 1024 tasks == blockDim, single pass covers both K and V.
    __syncthreads();

    const int s = s0 + qi;
    const float* Qp = g_q + (size_t)bh * SEQ * DHEAD + ((size_t)s << 6);

    const float scale = 0.125f;             // 1/sqrt(64)
    float q0 = Qp[lane] * scale;
    float q1 = Qp[lane + 32] * scale;

    const float NEGINF = -CUDART_INF_F;
    float l0 = NEGINF;
    int   i0 = 0;
    int   cnt  = 0;
    int   nAll = 0;

    const int t = s >> 8;
    const int r = (s >> 4) & 15;

#define PROC_NB(JEXPR, KRPTR)                                                 \
    {                                                                         \
        if ((nAll & 1) == parity) {                                           \
            const float* kr = (KRPTR);                                        \
            float pd = q0 * kr[lane] + q1 * kr[lane + 32];                    \
            pd += __shfl_xor_sync(FULLMASK, pd, 16);                          \
            pd += __shfl_xor_sync(FULLMASK, pd, 8);                           \
            pd += __shfl_xor_sync(FULLMASK, pd, 4);                           \
            pd += __shfl_xor_sync(FULLMASK, pd, 2);                           \
            pd += __shfl_xor_sync(FULLMASK, pd, 1);                           \
            if (lane == cnt) { l0 = pd; i0 = (JEXPR); }                       \
            cnt++;                                                            \
        }                                                                     \
        nAll++;                                                               \
    }

    const int dmax = min(LOCALB, s);
    for (int d = 0; d <= dmax; ++d) PROC_NB(s - d, &Kb[qi + LOCALB - d][0]);
    for (int m = 2; m <= r; ++m)    PROC_NB(s - 16 * m, Kp + ((size_t)(s - 16 * m) << 6));
    for (int m = 1; m <= t; ++m)    PROC_NB(s - 256 * m, Kp + ((size_t)(s - 256 * m) << 6));
#undef PROC_NB

    // partial softmax (this warp's cnt entries)
    float mx = l0;
    mx = fmaxf(mx, __shfl_xor_sync(FULLMASK, mx, 16));
    mx = fmaxf(mx, __shfl_xor_sync(FULLMASK, mx, 8));
    mx = fmaxf(mx, __shfl_xor_sync(FULLMASK, mx, 4));
    mx = fmaxf(mx, __shfl_xor_sync(FULLMASK, mx, 2));
    mx = fmaxf(mx, __shfl_xor_sync(FULLMASK, mx, 1));

    float e0 = (lane < cnt) ? __expf(l0 - mx) : 0.f;
    float ssum = e0;
    ssum += __shfl_xor_sync(FULLMASK, ssum, 16);
    ssum += __shfl_xor_sync(FULLMASK, ssum, 8);
    ssum += __shfl_xor_sync(FULLMASK, ssum, 4);
    ssum += __shfl_xor_sync(FULLMASK, ssum, 2);
    ssum += __shfl_xor_sync(FULLMASK, ssum, 1);

    if (lane == 0) MS[qi][parity] = make_float2(mx, ssum);
    __syncthreads();

    const float2 ms0 = MS[qi][0];
    const float2 ms1 = MS[qi][1];
    const float  M   = fmaxf(ms0.x, ms1.x);
    const float  f0  = (ms0.x == NEGINF) ? 0.f : __expf(ms0.x - M);
    const float  f1  = (ms1.x == NEGINF) ? 0.f : __expf(ms1.x - M);
    const float  S   = ms0.y * f0 + ms1.y * f1;
    const float  fp  = parity ? f1 : f0;

    // partial V accumulation (this warp's slots)
    float acc0 = 0.f, acc1 = 0.f;
    for (int n = 0; n < cnt; ++n) {
        float pe = __shfl_sync(FULLMASK, e0, n);
        int   j  = __shfl_sync(FULLMASK, i0, n);
        int   d  = s - j;
        const float* vr = (d <= LOCALB) ? &Vb[qi + LOCALB - d][0]
                                        : (Vp + ((size_t)j << 6));
        acc0 = fmaf(pe, vr[lane], acc0);
        acc1 = fmaf(pe, vr[lane + 32], acc1);
    }
    AccS[qi][parity][lane]      = acc0 * fp;
    AccS[qi][parity][lane + 32] = acc1 * fp;
    __syncthreads();

    if (parity == 0) {
        float inv = 1.0f / S;
        float o0 = (AccS[qi][0][lane]      + AccS[qi][1][lane])      * inv;
        float o1 = (AccS[qi][0][lane + 32] + AccS[qi][1][lane + 32]) * inv;
        int b = bh >> 3, h = bh & 7;
        size_t o = ((size_t)(b * SEQ + s) * DIM) + h * DHEAD + lane;
        g_att[o]      = o0;
        g_att[o + 32] = o1;
    }
}

// ---------------------------------------------------------------------------
extern "C" void kernel_launch(void* const* d_in, const int* in_sizes, int n_in,
                              void* d_out, int out_size)
{
    const float* query = (const float*)d_in[0];
    const float* key   = (const float*)d_in[1];
    const float* value = (const float*)d_in[2];
    const float* Wq    = (const float*)d_in[3];
    const float* bq    = (const float*)d_in[4];
    const float* Wk    = (const float*)d_in[5];
    const float* bk    = (const float*)d_in[6];
    const float* Wv    = (const float*)d_in[7];
    const float* bv    = (const float*)d_in[8];
    const float* Wo    = (const float*)d_in[9];
    const float* bo    = (const float*)d_in[10];
    float* out = (float*)d_out;

    dim3 blk(256);
    dim3 gridP(DIM / 128, MROWS / 128, 3);   // 4 x 64 x 3
    proj_qkv_kernel<<<gridP, blk>>>(query, key, value, Wq, Wk, Wv, bq, bk, bv);

    dim3 gridA(BATCH * HEADS * (SEQ / AQ));  // 4096 blocks, 1024 threads
    sparse_attn_kernel<<<gridA, dim3(1024)>>>();

    dim3 gridO(DIM / 128, MROWS / 128);      // 4 x 64
    out_proj_kernel<<<gridO, blk>>>(Wo, bo, out);
}

// round 9
// speedup vs baseline: 1.0561x; 1.0561x over previous
#include <cuda_runtime.h>
#include <cuda_bf16.h>
#include <math_constants.h>
#include <cstdint>
#include <cstddef>

// Problem constants
#define BATCH   8
#define SEQ     1024
#define DIM     512
#define HEADS   8
#define DHEAD   64
#define MROWS   (BATCH * SEQ)        // 8192
#define LOCALB  16

// Scratch (device globals; allocation is forbidden)
__device__ float g_q[MROWS * DIM];    // head-split [b][h][s][d]
__device__ float g_k[MROWS * DIM];
__device__ float g_v[MROWS * DIM];
__device__ float g_att[MROWS * DIM];  // merged-head [b][s][h*64+d]

// ---------------------------------------------------------------------------
// tf32 tensor-core GEMM (R3/R5 proven): 128x128 tile, BK=16, double-buffered.
// ---------------------------------------------------------------------------
#define BK 16
#define APITCH 20
#define BPITCH 136

__device__ __forceinline__ uint32_t f2tf32(float f) {
    uint32_t r;
    asm("cvt.rna.tf32.f32 %0, %1;" : "=r"(r) : "f"(f));
    return r;
}

__device__ __forceinline__ void mma_tf32(
    float& c0, float& c1, float& c2, float& c3,
    uint32_t a0, uint32_t a1, uint32_t a2, uint32_t a3,
    uint32_t b0, uint32_t b1)
{
    asm volatile(
        "mma.sync.aligned.m16n8k8.row.col.f32.tf32.tf32.f32 "
        "{%0,%1,%2,%3}, {%4,%5,%6,%7}, {%8,%9}, {%0,%1,%2,%3};"
        : "+f"(c0), "+f"(c1), "+f"(c2), "+f"(c3)
        : "r"(a0), "r"(a1), "r"(a2), "r"(a3), "r"(b0), "r"(b1));
}

__device__ __forceinline__ void gemm_tf32_body(
    const float* __restrict__ A, const float* __restrict__ W,
    const float* __restrict__ bias, float* __restrict__ C,
    int headsplit, int bx, int by)
{
    __shared__ float As[2][128][APITCH];
    __shared__ float Bs[2][BK][BPITCH];

    const int tid  = threadIdx.x;
    const int warp = tid >> 5;
    const int lane = tid & 31;
    const int g    = lane >> 2;
    const int tig  = lane & 3;

    const int warp_m = warp >> 2;
    const int warp_n = warp & 3;

    const float* Aptr = A + (size_t)(by * 128) * DIM;
    const float* Wptr = W + bx * 128;

    const int arow = tid >> 2;
    const int ac4  = (tid & 3) * 4;
    const int brow = tid >> 5;
    const int bc4  = (tid & 31) * 4;

    float c[4][4][4];
#pragma unroll
    for (int i = 0; i < 4; i++)
#pragma unroll
        for (int j = 0; j < 4; j++)
#pragma unroll
            for (int r = 0; r < 4; r++) c[i][j][r] = 0.f;

    float4 ra0, ra1, rb0, rb1;

    auto loadG = [&](int k0) {
        ra0 = *(const float4*)(Aptr + (size_t)arow * DIM + k0 + ac4);
        ra1 = *(const float4*)(Aptr + (size_t)(arow + 64) * DIM + k0 + ac4);
        rb0 = *(const float4*)(Wptr + (size_t)(k0 + brow) * DIM + bc4);
        rb1 = *(const float4*)(Wptr + (size_t)(k0 + brow + 8) * DIM + bc4);
    };
    auto storeS = [&](int buf) {
        float4 t;
        t.x = __uint_as_float(f2tf32(ra0.x)); t.y = __uint_as_float(f2tf32(ra0.y));
        t.z = __uint_as_float(f2tf32(ra0.z)); t.w = __uint_as_float(f2tf32(ra0.w));
        *(float4*)&As[buf][arow][ac4] = t;
        t.x = __uint_as_float(f2tf32(ra1.x)); t.y = __uint_as_float(f2tf32(ra1.y));
        t.z = __uint_as_float(f2tf32(ra1.z)); t.w = __uint_as_float(f2tf32(ra1.w));
        *(float4*)&As[buf][arow + 64][ac4] = t;
        t.x = __uint_as_float(f2tf32(rb0.x)); t.y = __uint_as_float(f2tf32(rb0.y));
        t.z = __uint_as_float(f2tf32(rb0.z)); t.w = __uint_as_float(f2tf32(rb0.w));
        *(float4*)&Bs[buf][brow][bc4] = t;
        t.x = __uint_as_float(f2tf32(rb1.x)); t.y = __uint_as_float(f2tf32(rb1.y));
        t.z = __uint_as_float(f2tf32(rb1.z)); t.w = __uint_as_float(f2tf32(rb1.w));
        *(float4*)&Bs[buf][brow + 8][bc4] = t;
    };

    loadG(0);
    storeS(0);
    __syncthreads();

    const int NIT = DIM / BK;   // 32
    for (int it = 0; it < NIT; ++it) {
        const int buf = it & 1;
        if (it + 1 < NIT) loadG((it + 1) * BK);

#pragma unroll
        for (int kk = 0; kk < 2; ++kk) {
            const int kb = kk * 8;
            uint32_t af[4][4];
#pragma unroll
            for (int mi = 0; mi < 4; mi++) {
                const int rb = warp_m * 64 + mi * 16;
                af[mi][0] = __float_as_uint(As[buf][rb + g][kb + tig]);
                af[mi][1] = __float_as_uint(As[buf][rb + g + 8][kb + tig]);
                af[mi][2] = __float_as_uint(As[buf][rb + g][kb + tig + 4]);
                af[mi][3] = __float_as_uint(As[buf][rb + g + 8][kb + tig + 4]);
            }
            uint32_t bf[4][2];
#pragma unroll
            for (int nj = 0; nj < 4; nj++) {
                const int cb = warp_n * 32 + nj * 8;
                bf[nj][0] = __float_as_uint(Bs[buf][kb + tig][cb + g]);
                bf[nj][1] = __float_as_uint(Bs[buf][kb + tig + 4][cb + g]);
            }
#pragma unroll
            for (int mi = 0; mi < 4; mi++)
#pragma unroll
                for (int nj = 0; nj < 4; nj++)
                    mma_tf32(c[mi][nj][0], c[mi][nj][1], c[mi][nj][2], c[mi][nj][3],
                             af[mi][0], af[mi][1], af[mi][2], af[mi][3],
                             bf[nj][0], bf[nj][1]);
        }

        if (it + 1 < NIT) storeS((it + 1) & 1);
        __syncthreads();
    }

#pragma unroll
    for (int mi = 0; mi < 4; mi++) {
#pragma unroll
        for (int nj = 0; nj < 4; nj++) {
            const int cb = bx * 128 + warp_n * 32 + nj * 8 + tig * 2;
#pragma unroll
            for (int half = 0; half < 2; half++) {
                const int row = by * 128 + warp_m * 64 + mi * 16 + g + half * 8;
                float v0 = c[mi][nj][half * 2 + 0] + bias[cb];
                float v1 = c[mi][nj][half * 2 + 1] + bias[cb + 1];
                if (headsplit) {
                    int b = row >> 10, s = row & 1023;
                    int h = cb >> 6,  d = cb & 63;
                    size_t o = ((size_t)((b * HEADS + h) * SEQ + s) << 6) + d;
                    C[o]     = v0;
                    C[o + 1] = v1;
                } else {
                    C[(size_t)row * DIM + cb]     = v0;
                    C[(size_t)row * DIM + cb + 1] = v1;
                }
            }
        }
    }
}

__global__ __launch_bounds__(256, 2) void proj_qkv_kernel(
    const float* __restrict__ q,  const float* __restrict__ k,  const float* __restrict__ v,
    const float* __restrict__ Wq, const float* __restrict__ Wk, const float* __restrict__ Wv,
    const float* __restrict__ bq, const float* __restrict__ bk, const float* __restrict__ bv)
{
    const float* A; const float* W; const float* bias; float* C;
    if (blockIdx.z == 0)      { A = q; W = Wq; bias = bq; C = g_q; }
    else if (blockIdx.z == 1) { A = k; W = Wk; bias = bk; C = g_k; }
    else                      { A = v; W = Wv; bias = bv; C = g_v; }
    gemm_tf32_body(A, W, bias, C, 1, blockIdx.x, blockIdx.y);
}

__global__ __launch_bounds__(256, 2) void out_proj_kernel(
    const float* __restrict__ Wo, const float* __restrict__ bo, float* __restrict__ out)
{
    gemm_tf32_body(g_att, Wo, bo, out, 0, blockIdx.x, blockIdx.y);
}

// ---------------------------------------------------------------------------
// Sparse attention: R5 shell (AQ=32, warp/query, 1024 thr) + grouped
// phase-split. Group 1 = band (17 slots: lane d), Group 2 = row (lanes 17..30,
// slot = 15+m) + frame m=1 (lane 31), m=2,3 -> l1 lanes 0,1.
// Per group: all dot-partials first (MLP~17), then 17 pipelined reductions.
// ---------------------------------------------------------------------------
#define FULLMASK 0xffffffffu
#define AQ 32
#define BANDROWS (AQ + LOCALB)        // 48

__global__ __launch_bounds__(1024) void sparse_attn_kernel()
{
    __shared__ float Kb[BANDROWS][DHEAD];
    __shared__ float Vb[BANDROWS][DHEAD];

    const int warp = threadIdx.x >> 5;      // 0..31 = query offset
    const int lane = threadIdx.x & 31;
    const int s0   = (blockIdx.x & (SEQ / AQ - 1)) * AQ;
    const int bh   = blockIdx.x / (SEQ / AQ);
    const int base = s0 - LOCALB;

    const float* Kp = g_k + (size_t)bh * SEQ * DHEAD;
    const float* Vp = g_v + (size_t)bh * SEQ * DHEAD;

    // stage band rows [s0-16, s0+31], zero-fill j<0
    for (int task = threadIdx.x; task < BANDROWS * 16 * 2; task += 1024) {
        int which = task >= BANDROWS * 16;
        int tt    = which ? task - BANDROWS * 16 : task;
        int row   = tt >> 4;
        int c4    = (tt & 15) * 4;
        int j     = base + row;
        float4 val = make_float4(0.f, 0.f, 0.f, 0.f);
        if (j >= 0) val = *(const float4*)((which ? Vp : Kp) + ((size_t)j << 6) + c4);
        *(float4*)(which ? &Vb[row][c4] : &Kb[row][c4]) = val;
    }
    __syncthreads();

    const int s = s0 + warp;
    const float* Qp = g_q + (size_t)bh * SEQ * DHEAD + ((size_t)s << 6);

    const float scale = 0.125f;             // 1/sqrt(64)
    float q0 = Qp[lane] * scale;
    float q1 = Qp[lane + 32] * scale;

    const int t    = s >> 8;
    const int r    = (s >> 4) & 15;
    const int dmax = min(LOCALB, s);        // warp-uniform

    const float NEGINF = -CUDART_INF_F;
    float l0 = NEGINF, l1 = NEGINF;
    float pd[17];

    // ===== Group 1: band neighbors d=0..16 =====
#pragma unroll
    for (int d = 0; d <= 16; ++d) {
        const float* kr = &Kb[warp + LOCALB - d][0];
        pd[d] = q0 * kr[lane] + q1 * kr[lane + 32];
    }
#pragma unroll
    for (int d = 0; d <= 16; ++d) {
        float p = pd[d];
        p += __shfl_xor_sync(FULLMASK, p, 16);
        p += __shfl_xor_sync(FULLMASK, p, 8);
        p += __shfl_xor_sync(FULLMASK, p, 4);
        p += __shfl_xor_sync(FULLMASK, p, 2);
        p += __shfl_xor_sync(FULLMASK, p, 1);
        pd[d] = p;                          // all lanes hold logit d
    }
#pragma unroll
    for (int d = 0; d <= 16; ++d)
        if (d <= dmax && lane == d) l0 = pd[d];

    // ===== Group 2: row m=2..15 (idx m-2) + frame m=1..3 (idx 13+m) =====
#pragma unroll
    for (int m = 2; m <= 15; ++m) {
        float v = 0.f;
        if (m <= r) {                       // warp-uniform
            const float* kr = Kp + ((size_t)(s - 16 * m) << 6);
            v = q0 * kr[lane] + q1 * kr[lane + 32];
        }
        pd[m - 2] = v;
    }
#pragma unroll
    for (int m = 1; m <= 3; ++m) {
        float v = 0.f;
        if (m <= t) {                       // warp-uniform
            const float* kr = Kp + ((size_t)(s - 256 * m) << 6);
            v = q0 * kr[lane] + q1 * kr[lane + 32];
        }
        pd[13 + m] = v;
    }
#pragma unroll
    for (int i = 0; i < 17; ++i) {
        float p = pd[i];
        p += __shfl_xor_sync(FULLMASK, p, 16);
        p += __shfl_xor_sync(FULLMASK, p, 8);
        p += __shfl_xor_sync(FULLMASK, p, 4);
        p += __shfl_xor_sync(FULLMASK, p, 2);
        p += __shfl_xor_sync(FULLMASK, p, 1);
        pd[i] = p;
    }
#pragma unroll
    for (int m = 2; m <= 15; ++m)
        if (m <= r && lane == 15 + m) l0 = pd[m - 2];
    if (t >= 1 && lane == 31) l0 = pd[14];
    if (t >= 2 && lane == 0)  l1 = pd[15];
    if (t >= 3 && lane == 1)  l1 = pd[16];

    // ===== softmax over lane-distributed logits =====
    float mx = fmaxf(l0, l1);
    mx = fmaxf(mx, __shfl_xor_sync(FULLMASK, mx, 16));
    mx = fmaxf(mx, __shfl_xor_sync(FULLMASK, mx, 8));
    mx = fmaxf(mx, __shfl_xor_sync(FULLMASK, mx, 4));
    mx = fmaxf(mx, __shfl_xor_sync(FULLMASK, mx, 2));
    mx = fmaxf(mx, __shfl_xor_sync(FULLMASK, mx, 1));

    float e0 = __expf(l0 - mx);             // -inf -> 0
    float e1 = __expf(l1 - mx);
    float ssum = e0 + e1;
    ssum += __shfl_xor_sync(FULLMASK, ssum, 16);
    ssum += __shfl_xor_sync(FULLMASK, ssum, 8);
    ssum += __shfl_xor_sync(FULLMASK, ssum, 4);
    ssum += __shfl_xor_sync(FULLMASK, ssum, 2);
    ssum += __shfl_xor_sync(FULLMASK, ssum, 1);

    // ===== V accumulation (unrolled, pipelined loads) =====
    float acc0 = 0.f, acc1 = 0.f;
#pragma unroll
    for (int d = 0; d <= 16; ++d) {
        float pe = __shfl_sync(FULLMASK, e0, d);   // 0 for invalid d
        const float* vr = &Vb[warp + LOCALB - d][0];
        acc0 = fmaf(pe, vr[lane], acc0);
        acc1 = fmaf(pe, vr[lane + 32], acc1);
    }
#pragma unroll
    for (int m = 2; m <= 15; ++m) {
        if (m <= r) {                       // warp-uniform
            float pe = __shfl_sync(FULLMASK, e0, 15 + m);
            const float* vr = Vp + ((size_t)(s - 16 * m) << 6);
            acc0 = fmaf(pe, vr[lane], acc0);
            acc1 = fmaf(pe, vr[lane + 32], acc1);
        }
    }
    if (t >= 1) {
        float pe = __shfl_sync(FULLMASK, e0, 31);
        const float* vr = Vp + ((size_t)(s - 256) << 6);
        acc0 = fmaf(pe, vr[lane], acc0);
        acc1 = fmaf(pe, vr[lane + 32], acc1);
    }
    if (t >= 2) {
        float pe = __shfl_sync(FULLMASK, e1, 0);
        const float* vr = Vp + ((size_t)(s - 512) << 6);
        acc0 = fmaf(pe, vr[lane], acc0);
        acc1 = fmaf(pe, vr[lane + 32], acc1);
    }
    if (t >= 3) {
        float pe = __shfl_sync(FULLMASK, e1, 1);
        const float* vr = Vp + ((size_t)(s - 768) << 6);
        acc0 = fmaf(pe, vr[lane], acc0);
        acc1 = fmaf(pe, vr[lane + 32], acc1);
    }

    float inv = 1.0f / ssum;
    int b = bh >> 3, h = bh & 7;
    size_t o = ((size_t)(b * SEQ + s) * DIM) + h * DHEAD + lane;
    g_att[o]      = acc0 * inv;
    g_att[o + 32] = acc1 * inv;
}

// ---------------------------------------------------------------------------
extern "C" void kernel_launch(void* const* d_in, const int* in_sizes, int n_in,
                              void* d_out, int out_size)
{
    const float* query = (const float*)d_in[0];
    const float* key   = (const float*)d_in[1];
    const float* value = (const float*)d_in[2];
    const float* Wq    = (const float*)d_in[3];
    const float* bq    = (const float*)d_in[4];
    const float* Wk    = (const float*)d_in[5];
    const float* bk    = (const float*)d_in[6];
    const float* Wv    = (const float*)d_in[7];
    const float* bv    = (const float*)d_in[8];
    const float* Wo    = (const float*)d_in[9];
    const float* bo    = (const float*)d_in[10];
    float* out = (float*)d_out;

    dim3 blk(256);
    dim3 gridP(DIM / 128, MROWS / 128, 3);   // 4 x 64 x 3
    proj_qkv_kernel<<<gridP, blk>>>(query, key, value, Wq, Wk, Wv, bq, bk, bv);

    dim3 gridA(BATCH * HEADS * (SEQ / AQ));  // 2048 blocks, 1024 threads
    sparse_attn_kernel<<<gridA, dim3(1024)>>>();

    dim3 gridO(DIM / 128, MROWS / 128);      // 4 x 64
    out_proj_kernel<<<gridO, blk>>>(Wo, bo, out);
}

// round 10
// speedup vs baseline: 1.2570x; 1.1903x over previous
#include <cuda_runtime.h>
#include <cuda_bf16.h>
#include <math_constants.h>
#include <cstdint>
#include <cstddef>

// Problem constants
#define BATCH   8
#define SEQ     1024
#define DIM     512
#define HEADS   8
#define DHEAD   64
#define MROWS   (BATCH * SEQ)        // 8192
#define LOCALB  16

// Scratch (device globals; allocation is forbidden)
__device__ float g_q[MROWS * DIM];     // head-split [b][h][s][d]  (fp32)
__device__ float g_k[MROWS * DIM];
__device__ float g_v[MROWS * DIM];
__device__ float g_att[MROWS * DIM];   // merged-head, tf32-valued fp32
__device__ float g_qc[MROWS * DIM];    // tf32-converted inputs
__device__ float g_kc[MROWS * DIM];
__device__ float g_vc[MROWS * DIM];
__device__ float g_wc[4 * DIM * DIM];  // tf32-converted Wq,Wk,Wv,Wo

__device__ __forceinline__ uint32_t f2tf32(float f) {
    uint32_t r;
    asm("cvt.rna.tf32.f32 %0, %1;" : "=r"(r) : "f"(f));
    return r;
}
__device__ __forceinline__ uint32_t smem_u32(const void* p) {
    uint32_t a;
    asm("{ .reg .u64 t; cvta.to.shared.u64 t, %1; cvt.u32.u64 %0, t; }" : "=r"(a) : "l"(p));
    return a;
}
__device__ __forceinline__ void cp_async16(uint32_t dst, const void* src) {
    asm volatile("cp.async.cg.shared.global [%0], [%1], 16;" :: "r"(dst), "l"(src));
}
#define CP_COMMIT() asm volatile("cp.async.commit_group;" ::: "memory")
#define CP_WAIT2()  asm volatile("cp.async.wait_group 2;" ::: "memory")

// ---------------------------------------------------------------------------
// Pre-convert kernel: q,k,v inputs and 4 weight matrices -> RNA tf32 values.
// ---------------------------------------------------------------------------
#define ACT_F4 (MROWS * DIM / 4)       // 1,048,576 float4 per activation
#define W_F4   (DIM * DIM / 4)         // 65,536 float4 per weight
#define CONV_F4 (3 * ACT_F4 + 4 * W_F4)

__global__ __launch_bounds__(256) void convert_tf32_kernel(
    const float4* __restrict__ q, const float4* __restrict__ k,
    const float4* __restrict__ v,
    const float4* __restrict__ Wq, const float4* __restrict__ Wk,
    const float4* __restrict__ Wv, const float4* __restrict__ Wo)
{
    int i = blockIdx.x * blockDim.x + threadIdx.x;
    if (i >= CONV_F4) return;
    const float4* src;
    float4* dst;
    int off;
    if (i < ACT_F4)                { src = q;  dst = (float4*)g_qc; off = i; }
    else if (i < 2 * ACT_F4)       { src = k;  dst = (float4*)g_kc; off = i - ACT_F4; }
    else if (i < 3 * ACT_F4)       { src = v;  dst = (float4*)g_vc; off = i - 2 * ACT_F4; }
    else {
        int wi = i - 3 * ACT_F4;               // 0 .. 4*W_F4-1
        int w  = wi / W_F4;
        off = wi - w * W_F4;
        src = (w == 0) ? Wq : (w == 1) ? Wk : (w == 2) ? Wv : Wo;
        dst = (float4*)(g_wc + (size_t)w * DIM * DIM);
    }
    float4 a = src[off];
    float4 t;
    t.x = __uint_as_float(f2tf32(a.x));
    t.y = __uint_as_float(f2tf32(a.y));
    t.z = __uint_as_float(f2tf32(a.z));
    t.w = __uint_as_float(f2tf32(a.w));
    dst[off] = t;
}

// ---------------------------------------------------------------------------
// tf32 tensor-core GEMM with cp.async 4-stage pipeline.
// C[M,512] = A[M,512] @ W[512,512] + bias.  A, W already tf32-valued.
// 128x128 tile, BK=16, 8 warps x (64x32) of m16n8k8.
// ---------------------------------------------------------------------------
#define BK 16
#define APITCH 20
#define BPITCH 136
#define STAGES 4
#define AS_STRIDE (128 * APITCH)               // floats per A stage (2560)
#define BS_STRIDE (BK * BPITCH)                // floats per B stage (2176)
#define AS_BYTES  (STAGES * AS_STRIDE * 4)     // 40960
#define GEMM_SMEM ((STAGES * (AS_STRIDE + BS_STRIDE)) * 4)   // 75776

__device__ __forceinline__ void mma_tf32(
    float& c0, float& c1, float& c2, float& c3,
    uint32_t a0, uint32_t a1, uint32_t a2, uint32_t a3,
    uint32_t b0, uint32_t b1)
{
    asm volatile(
        "mma.sync.aligned.m16n8k8.row.col.f32.tf32.tf32.f32 "
        "{%0,%1,%2,%3}, {%4,%5,%6,%7}, {%8,%9}, {%0,%1,%2,%3};"
        : "+f"(c0), "+f"(c1), "+f"(c2), "+f"(c3)
        : "r"(a0), "r"(a1), "r"(a2), "r"(a3), "r"(b0), "r"(b1));
}

__device__ __forceinline__ void gemm_tf32_body(
    const float* __restrict__ A, const float* __restrict__ W,
    const float* __restrict__ bias, float* __restrict__ C,
    int headsplit, int bx, int by)
{
    extern __shared__ float dynsmem[];
    float* As = dynsmem;                          // [STAGES][128][APITCH]
    float* Bs = dynsmem + STAGES * AS_STRIDE;     // [STAGES][BK][BPITCH]
    const uint32_t sbase = smem_u32(dynsmem);

    const int tid  = threadIdx.x;
    const int warp = tid >> 5;
    const int lane = tid & 31;
    const int g    = lane >> 2;
    const int tig  = lane & 3;
    const int warp_m = warp >> 2;
    const int warp_n = warp & 3;

    const float* Aptr = A + (size_t)(by * 128) * DIM;
    const float* Wptr = W + bx * 128;

    const int arow = tid >> 2;             // 0..63 (+64)
    const int ac4  = (tid & 3) * 4;
    const int brow = tid >> 5;             // 0..7  (+8)
    const int bc4  = (tid & 31) * 4;

    // per-thread smem byte offsets (stage 0)
    const uint32_t a_d0 = sbase + (arow * APITCH + ac4) * 4;
    const uint32_t a_d1 = sbase + ((arow + 64) * APITCH + ac4) * 4;
    const uint32_t b_d0 = sbase + AS_BYTES + (brow * BPITCH + bc4) * 4;
    const uint32_t b_d1 = sbase + AS_BYTES + ((brow + 8) * BPITCH + bc4) * 4;

    float c[4][4][4];
#pragma unroll
    for (int i = 0; i < 4; i++)
#pragma unroll
        for (int j = 0; j < 4; j++)
#pragma unroll
            for (int r = 0; r < 4; r++) c[i][j][r] = 0.f;

    auto issue_stage = [&](int stage, int k0) {
        uint32_t ao = stage * (AS_STRIDE * 4);
        uint32_t bo = stage * (BS_STRIDE * 4);
        cp_async16(a_d0 + ao, Aptr + (size_t)arow * DIM + k0 + ac4);
        cp_async16(a_d1 + ao, Aptr + (size_t)(arow + 64) * DIM + k0 + ac4);
        cp_async16(b_d0 + bo, Wptr + (size_t)(k0 + brow) * DIM + bc4);
        cp_async16(b_d1 + bo, Wptr + (size_t)(k0 + brow + 8) * DIM + bc4);
    };

    const int NIT = DIM / BK;   // 32
    // prologue: stages 0..2
    issue_stage(0, 0);          CP_COMMIT();
    issue_stage(1, BK);         CP_COMMIT();
    issue_stage(2, 2 * BK);     CP_COMMIT();

    for (int it = 0; it < NIT; ++it) {
        CP_WAIT2();             // group 'it' complete (pending <= 2)
        __syncthreads();        // all threads' stage-it data visible; all past it-1

        const float* Ab = As + (it & 3) * AS_STRIDE;
        const float* Bb = Bs + (it & 3) * BS_STRIDE;
#pragma unroll
        for (int kk = 0; kk < 2; ++kk) {
            const int kb = kk * 8;
            uint32_t af[4][4];
#pragma unroll
            for (int mi = 0; mi < 4; mi++) {
                const int rb = warp_m * 64 + mi * 16;
                af[mi][0] = __float_as_uint(Ab[(rb + g) * APITCH + kb + tig]);
                af[mi][1] = __float_as_uint(Ab[(rb + g + 8) * APITCH + kb + tig]);
                af[mi][2] = __float_as_uint(Ab[(rb + g) * APITCH + kb + tig + 4]);
                af[mi][3] = __float_as_uint(Ab[(rb + g + 8) * APITCH + kb + tig + 4]);
            }
            uint32_t bf[4][2];
#pragma unroll
            for (int nj = 0; nj < 4; nj++) {
                const int cb = warp_n * 32 + nj * 8;
                bf[nj][0] = __float_as_uint(Bb[(kb + tig) * BPITCH + cb + g]);
                bf[nj][1] = __float_as_uint(Bb[(kb + tig + 4) * BPITCH + cb + g]);
            }
#pragma unroll
            for (int mi = 0; mi < 4; mi++)
#pragma unroll
                for (int nj = 0; nj < 4; nj++)
                    mma_tf32(c[mi][nj][0], c[mi][nj][1], c[mi][nj][2], c[mi][nj][3],
                             af[mi][0], af[mi][1], af[mi][2], af[mi][3],
                             bf[nj][0], bf[nj][1]);
        }

        // prefetch stage it+3 (writes buffer (it-1)&3 — safe past the barrier)
        if (it + 3 < NIT) issue_stage((it + 3) & 3, (it + 3) * BK);
        CP_COMMIT();            // empty commits at tail keep group count exact
    }

    // Epilogue
#pragma unroll
    for (int mi = 0; mi < 4; mi++) {
#pragma unroll
        for (int nj = 0; nj < 4; nj++) {
            const int cb = bx * 128 + warp_n * 32 + nj * 8 + tig * 2;
#pragma unroll
            for (int half = 0; half < 2; half++) {
                const int row = by * 128 + warp_m * 64 + mi * 16 + g + half * 8;
                float v0 = c[mi][nj][half * 2 + 0] + bias[cb];
                float v1 = c[mi][nj][half * 2 + 1] + bias[cb + 1];
                if (headsplit) {
                    int b = row >> 10, s = row & 1023;
                    int h = cb >> 6,  d = cb & 63;
                    size_t o = ((size_t)((b * HEADS + h) * SEQ + s) << 6) + d;
                    C[o]     = v0;
                    C[o + 1] = v1;
                } else {
                    C[(size_t)row * DIM + cb]     = v0;
                    C[(size_t)row * DIM + cb + 1] = v1;
                }
            }
        }
    }
}

__global__ __launch_bounds__(256, 2) void proj_qkv_kernel(
    const float* __restrict__ bq, const float* __restrict__ bk, const float* __restrict__ bv)
{
    const float* A; const float* W; const float* bias; float* C;
    if (blockIdx.z == 0)      { A = g_qc; W = g_wc;                   bias = bq; C = g_q; }
    else if (blockIdx.z == 1) { A = g_kc; W = g_wc + DIM * DIM;       bias = bk; C = g_k; }
    else                      { A = g_vc; W = g_wc + 2 * DIM * DIM;   bias = bv; C = g_v; }
    gemm_tf32_body(A, W, bias, C, 1, blockIdx.x, blockIdx.y);
}

__global__ __launch_bounds__(256, 2) void out_proj_kernel(
    const float* __restrict__ bo, float* __restrict__ out)
{
    gemm_tf32_body(g_att, g_wc + 3 * DIM * DIM, bo, out, 0, blockIdx.x, blockIdx.y);
}

// ---------------------------------------------------------------------------
// Sparse attention (R5 proven version, verbatim; only the final stores now
// write tf32-rounded values so out_proj can cp.async them raw).
// ---------------------------------------------------------------------------
#define FULLMASK 0xffffffffu
#define AQ 32
#define BANDROWS (AQ + LOCALB)        // 48

__global__ __launch_bounds__(1024) void sparse_attn_kernel()
{
    __shared__ float Kb[BANDROWS][DHEAD];
    __shared__ float Vb[BANDROWS][DHEAD];

    const int warp = threadIdx.x >> 5;
    const int lane = threadIdx.x & 31;
    const int s0   = (blockIdx.x & (SEQ / AQ - 1)) * AQ;
    const int bh   = blockIdx.x / (SEQ / AQ);
    const int base = s0 - LOCALB;

    const float* Kp = g_k + (size_t)bh * SEQ * DHEAD;
    const float* Vp = g_v + (size_t)bh * SEQ * DHEAD;

    for (int task = threadIdx.x; task < BANDROWS * 16 * 2; task += 1024) {
        int which = task >= BANDROWS * 16;
        int tt    = which ? task - BANDROWS * 16 : task;
        int row   = tt >> 4;
        int c4    = (tt & 15) * 4;
        int j     = base + row;
        if (j >= 0) {
            const float* src = (which ? Vp : Kp) + ((size_t)j << 6) + c4;
            float4 val = *(const float4*)src;
            float* dst = which ? &Vb[row][c4] : &Kb[row][c4];
            *(float4*)dst = val;
        }
    }
    __syncthreads();

    const int s  = s0 + warp;
    const float* Qp = g_q + (size_t)bh * SEQ * DHEAD + ((size_t)s << 6);

    const float scale = 0.125f;
    float q0 = Qp[lane] * scale;
    float q1 = Qp[lane + 32] * scale;

    const float NEGINF = -CUDART_INF_F;
    float l0 = NEGINF, l1 = NEGINF;
    int   i0 = 0,      i1 = 0;
    int   count = 0;

    const int t = s >> 8;
    const int r = (s >> 4) & 15;

#define PROC_ROW(KRPTR, JIDX)                                                 \
    {                                                                         \
        const float* kr = (KRPTR);                                            \
        float p = q0 * kr[lane] + q1 * kr[lane + 32];                         \
        p += __shfl_xor_sync(FULLMASK, p, 16);                                \
        p += __shfl_xor_sync(FULLMASK, p, 8);                                 \
        p += __shfl_xor_sync(FULLMASK, p, 4);                                 \
        p += __shfl_xor_sync(FULLMASK, p, 2);                                 \
        p += __shfl_xor_sync(FULLMASK, p, 1);                                 \
        if (count < 32) { if (lane == count) { l0 = p; i0 = (JIDX); } }       \
        else            { if (lane == count - 32) { l1 = p; i1 = (JIDX); } }  \
        count++;                                                              \
    }

    const int dmax  = min(LOCALB, s);
    const int nBand = dmax + 1;
    for (int d = 0; d <= dmax; ++d) PROC_ROW(&Kb[warp + LOCALB - d][0], s - d);
    for (int m = 2; m <= r; ++m)    PROC_ROW(Kp + ((size_t)(s - 16 * m) << 6), s - 16 * m);
    for (int m = 1; m <= t; ++m)    PROC_ROW(Kp + ((size_t)(s - 256 * m) << 6), s - 256 * m);
#undef PROC_ROW

    float mx = fmaxf(l0, l1);
    mx = fmaxf(mx, __shfl_xor_sync(FULLMASK, mx, 16));
    mx = fmaxf(mx, __shfl_xor_sync(FULLMASK, mx, 8));
    mx = fmaxf(mx, __shfl_xor_sync(FULLMASK, mx, 4));
    mx = fmaxf(mx, __shfl_xor_sync(FULLMASK, mx, 2));
    mx = fmaxf(mx, __shfl_xor_sync(FULLMASK, mx, 1));

    float e0 = __expf(l0 - mx);
    float e1 = __expf(l1 - mx);
    float ssum = e0 + e1;
    ssum += __shfl_xor_sync(FULLMASK, ssum, 16);
    ssum += __shfl_xor_sync(FULLMASK, ssum, 8);
    ssum += __shfl_xor_sync(FULLMASK, ssum, 4);
    ssum += __shfl_xor_sync(FULLMASK, ssum, 2);
    ssum += __shfl_xor_sync(FULLMASK, ssum, 1);

    float acc0 = 0.f, acc1 = 0.f;
    for (int n = 0; n < nBand; ++n) {
        float p = __shfl_sync(FULLMASK, e0, n);
        const float* vr = &Vb[warp + LOCALB - n][0];
        acc0 = fmaf(p, vr[lane], acc0);
        acc1 = fmaf(p, vr[lane + 32], acc1);
    }
    for (int n = nBand; n < count; ++n) {
        float e = (n < 32) ? e0 : e1;
        int   jj = (n < 32) ? i0 : i1;
        float p = __shfl_sync(FULLMASK, e, n & 31);
        int   j = __shfl_sync(FULLMASK, jj, n & 31);
        const float* vr = Vp + ((size_t)j << 6);
        acc0 = fmaf(p, vr[lane], acc0);
        acc1 = fmaf(p, vr[lane + 32], acc1);
    }

    float inv = 1.0f / ssum;
    int b = bh >> 3, h = bh & 7;
    size_t o = ((size_t)(b * SEQ + s) * DIM) + h * DHEAD + lane;
    g_att[o]      = __uint_as_float(f2tf32(acc0 * inv));
    g_att[o + 32] = __uint_as_float(f2tf32(acc1 * inv));
}

// ---------------------------------------------------------------------------
extern "C" void kernel_launch(void* const* d_in, const int* in_sizes, int n_in,
                              void* d_out, int out_size)
{
    const float* query = (const float*)d_in[0];
    const float* key   = (const float*)d_in[1];
    const float* value = (const float*)d_in[2];
    const float* Wq    = (const float*)d_in[3];
    const float* bq    = (const float*)d_in[4];
    const float* Wk    = (const float*)d_in[5];
    const float* bk    = (const float*)d_in[6];
    const float* Wv    = (const float*)d_in[7];
    const float* bv    = (const float*)d_in[8];
    const float* Wo    = (const float*)d_in[9];
    const float* bo    = (const float*)d_in[10];
    float* out = (float*)d_out;

    cudaFuncSetAttribute(proj_qkv_kernel, cudaFuncAttributeMaxDynamicSharedMemorySize, GEMM_SMEM);
    cudaFuncSetAttribute(out_proj_kernel, cudaFuncAttributeMaxDynamicSharedMemorySize, GEMM_SMEM);

    // 1) pre-convert inputs + weights to RNA tf32
    convert_tf32_kernel<<<(CONV_F4 + 255) / 256, 256>>>(
        (const float4*)query, (const float4*)key, (const float4*)value,
        (const float4*)Wq, (const float4*)Wk, (const float4*)Wv, (const float4*)Wo);

    // 2) QKV projections
    dim3 blk(256);
    dim3 gridP(DIM / 128, MROWS / 128, 3);   // 4 x 64 x 3
    proj_qkv_kernel<<<gridP, blk, GEMM_SMEM>>>(bq, bk, bv);

    // 3) sparse attention
    dim3 gridA(BATCH * HEADS * (SEQ / AQ));  // 2048 blocks, 1024 threads
    sparse_attn_kernel<<<gridA, dim3(1024)>>>();

    // 4) output projection
    dim3 gridO(DIM / 128, MROWS / 128);      // 4 x 64
    out_proj_kernel<<<gridO, blk, GEMM_SMEM>>>(bo, out);
}